// round 9
// baseline (speedup 1.0000x reference)
#include <cuda_runtime.h>
#include <cstdint>

// ---------------------------------------------------------------------------
// KeyedGRU  (B=64, T=2048, I=H=256, KB=4, KL=16)  -- all fp32
// A: gi GEMM (unchanged from R7, ~1.06ms).
// B: key scan (unchanged, validated).
// C: main scan v3 -- row-partitioned (R8 design) with termination fix:
//    final-step broadcast skipped + trailing cluster sync, so no st.async
//    traffic can be in flight when a CTA exits (R8 ULF root cause).
// ---------------------------------------------------------------------------

#define T_STEPS 2048
#define BATCH   64
#define HID     256
#define ROWS_MAIN (T_STEPS * BATCH)
#define ROWS_ALL  (ROWS_MAIN + 64)
#define CSIZE 4
#define RPC   192
#define WS    260

__device__ float g_gi[(size_t)ROWS_ALL * 768];
__device__ float g_gates[16 * HID];

typedef unsigned long long ull;

// ---------------- helpers ----------------
__device__ __forceinline__ uint32_t smem_u32(const void* p) {
    uint32_t a;
    asm("{ .reg .u64 t; cvta.to.shared.u64 t, %1; cvt.u32.u64 %0, t; }"
        : "=r"(a) : "l"(p));
    return a;
}
__device__ __forceinline__ void st_cluster_f32(uint32_t laddr, uint32_t rank, float v) {
    uint32_t ra;
    asm volatile("mapa.shared::cluster.u32 %0, %1, %2;" : "=r"(ra) : "r"(laddr), "r"(rank));
    asm volatile("st.shared::cluster.f32 [%0], %1;" :: "r"(ra), "f"(v) : "memory");
}
__device__ __forceinline__ uint32_t mapa_addr(uint32_t laddr, uint32_t rank) {
    uint32_t ra;
    asm("mapa.shared::cluster.u32 %0, %1, %2;" : "=r"(ra) : "r"(laddr), "r"(rank));
    return ra;
}
__device__ __forceinline__ void st_async_2f(uint32_t ra, float a, float b, uint32_t rbar) {
    asm volatile("{ .reg .b64 d; mov.b64 d, {%1, %2};\n\t"
                 "st.async.shared::cluster.mbarrier::complete_tx::bytes.b64 [%0], d, [%3]; }"
                 :: "r"(ra), "f"(a), "f"(b), "r"(rbar) : "memory");
}
__device__ __forceinline__ void mbar_init(uint32_t a, uint32_t cnt) {
    asm volatile("mbarrier.init.shared.b64 [%0], %1;" :: "r"(a), "r"(cnt) : "memory");
}
__device__ __forceinline__ void mbar_arrive_expect(uint32_t a, uint32_t tx) {
    asm volatile("mbarrier.arrive.expect_tx.shared.b64 _, [%0], %1;"
                 :: "r"(a), "r"(tx) : "memory");
}
__device__ __forceinline__ void mbar_wait_parity(uint32_t mbar, uint32_t parity) {
    uint32_t done;
    asm volatile("{\n\t.reg .pred p;\n\t"
                 "mbarrier.try_wait.parity.acquire.cluster.shared::cta.b64 p, [%1], %2;\n\t"
                 "selp.b32 %0, 1, 0, p;\n\t}"
                 : "=r"(done) : "r"(mbar), "r"(parity) : "memory");
    if (!done) {
        asm volatile("{\n\t.reg .pred P1;\n\t"
                     "WAIT_LOOP_%=:\n\t"
                     "mbarrier.try_wait.parity.acquire.cluster.shared::cta.b64 P1, [%0], %1, 0x989680;\n\t"
                     "@P1 bra.uni WAIT_DONE_%=;\n\t"
                     "bra.uni WAIT_LOOP_%=;\n\t"
                     "WAIT_DONE_%=:\n\t}"
                     :: "r"(mbar), "r"(parity) : "memory");
    }
}
__device__ __forceinline__ void cluster_sync_() {
    asm volatile("barrier.cluster.arrive.aligned;" ::: "memory");
    asm volatile("barrier.cluster.wait.aligned;" ::: "memory");
}
__device__ __forceinline__ uint32_t ctarank() {
    uint32_t r; asm("mov.u32 %0, %%cluster_ctarank;" : "=r"(r)); return r;
}
__device__ __forceinline__ ull dup2(float a) {
    ull d; asm("mov.b64 %0, {%1, %1};" : "=l"(d) : "f"(a)); return d;
}
__device__ __forceinline__ void fma2(ull& c, ull a, ull b) {
    asm("fma.rn.f32x2 %0, %1, %2, %0;" : "+l"(c) : "l"(a), "l"(b));
}
__device__ __forceinline__ void unpk(ull v, float& x, float& y) {
    asm("mov.b64 {%0, %1}, %2;" : "=f"(x), "=f"(y) : "l"(v));
}
__device__ __forceinline__ float sigm_(float x)  { return 1.0f / (1.0f + __expf(-x)); }
__device__ __forceinline__ float tanh_(float x)  { return 1.0f - __fdividef(2.0f, __expf(2.0f * x) + 1.0f); }
__device__ __forceinline__ float sigmoidf_(float x) { return 1.0f / (1.0f + expf(-x)); }

// ---------------------------------------------------------------------------
// Kernel A: unchanged from R7.
// ---------------------------------------------------------------------------
#define BR2 132

__global__ void __launch_bounds__(256, 2) kA(const float* __restrict__ x,
                                             const float* __restrict__ wmk,
                                             const float* __restrict__ wih,
                                             const float* __restrict__ bih)
{
    extern __shared__ __align__(16) float smA[];
    float (*As)[32][BR2] = (float (*)[32][BR2])smA;
    float (*Bs)[32][BR2] = (float (*)[32][BR2])(smA + 2 * 32 * BR2);

    const int tid = threadIdx.x;
    const int nt = blockIdx.x;
    const int rt = blockIdx.y;
    const int tx = tid & 15, ty = tid >> 4;
    const int m_base = rt * 128, n_base = nt * 128;

    ull acc[8][4];
    #pragma unroll
    for (int i = 0; i < 8; ++i)
        #pragma unroll
        for (int j = 0; j < 4; ++j) acc[i][j] = 0ull;

    float4 ra[4], rb[4];

    auto load_regs = [&](int kc) {
        const int kb = kc * 32;
        #pragma unroll
        for (int q = 0; q < 4; ++q) {
            int v = tid + q * 256;
            int m = v >> 3;
            int k4 = (v & 7) << 2;
            int row = m_base + m;
            if (row < ROWS_MAIN) {
                int t = row >> 6, b = row & 63;
                ra[q] = *(const float4*)&x[((size_t)b * T_STEPS + t) * 256 + kb + k4];
            } else if (row < ROWS_ALL) {
                int r2 = row - ROWS_MAIN;
                int l = r2 >> 2, kbk = r2 & 3;
                ra[q] = *(const float4*)&wmk[((size_t)kbk * 16 + l) * 256 + kb + k4];
            } else {
                ra[q] = make_float4(0.f, 0.f, 0.f, 0.f);
            }
            rb[q] = *(const float4*)&wih[(size_t)(n_base + m) * 256 + kb + k4];
        }
    };

    auto store_stage = [&](int buf) {
        #pragma unroll
        for (int q = 0; q < 4; ++q) {
            int v = tid + q * 256;
            int m = v >> 3;
            int k4 = (v & 7) << 2;
            const float* av = &ra[q].x;
            const float* bv = &rb[q].x;
            #pragma unroll
            for (int j = 0; j < 4; ++j) {
                As[buf][k4 + j][m] = av[j];
                Bs[buf][k4 + j][m] = bv[j];
            }
        }
    };

    load_regs(0);
    store_stage(0);
    __syncthreads();

    for (int kc = 0; kc < 8; ++kc) {
        if (kc < 7) load_regs(kc + 1);
        const int buf = kc & 1;
        #pragma unroll 8
        for (int k = 0; k < 32; ++k) {
            float4 a0 = *(const float4*)&As[buf][k][ty * 8 + 0];
            float4 a1 = *(const float4*)&As[buf][k][ty * 8 + 4];
            ulonglong2 b0 = *(const ulonglong2*)&Bs[buf][k][tx * 4];
            ulonglong2 b1 = *(const ulonglong2*)&Bs[buf][k][64 + tx * 4];
            ull ad[8];
            ad[0] = dup2(a0.x); ad[1] = dup2(a0.y); ad[2] = dup2(a0.z); ad[3] = dup2(a0.w);
            ad[4] = dup2(a1.x); ad[5] = dup2(a1.y); ad[6] = dup2(a1.z); ad[7] = dup2(a1.w);
            #pragma unroll
            for (int i = 0; i < 8; ++i) {
                fma2(acc[i][0], ad[i], b0.x);
                fma2(acc[i][1], ad[i], b0.y);
                fma2(acc[i][2], ad[i], b1.x);
                fma2(acc[i][3], ad[i], b1.y);
            }
        }
        if (kc < 7) {
            store_stage((kc + 1) & 1);
            __syncthreads();
        }
    }

    float4 bs0 = *(const float4*)&bih[n_base + tx * 4];
    float4 bs1 = *(const float4*)&bih[n_base + 64 + tx * 4];
    #pragma unroll
    for (int i = 0; i < 8; ++i) {
        int row = m_base + ty * 8 + i;
        if (row >= ROWS_ALL) break;
        float f0, f1, f2, f3;
        unpk(acc[i][0], f0, f1); unpk(acc[i][1], f2, f3);
        float4 o0 = make_float4(f0 + bs0.x, f1 + bs0.y, f2 + bs0.z, f3 + bs0.w);
        *(float4*)&g_gi[(size_t)row * 768 + n_base + tx * 4] = o0;
        unpk(acc[i][2], f0, f1); unpk(acc[i][3], f2, f3);
        float4 o1 = make_float4(f0 + bs1.x, f1 + bs1.y, f2 + bs1.z, f3 + bs1.w);
        *(float4*)&g_gi[(size_t)row * 768 + n_base + 64 + tx * 4] = o1;
    }
}

// ---------------------------------------------------------------------------
// Kernel B: key scan -- unchanged (validated).
// ---------------------------------------------------------------------------
__global__ void __launch_bounds__(256, 1) __cluster_dims__(CSIZE, 1, 1)
kB(const float* __restrict__ whh, const float* __restrict__ bhh)
{
    extern __shared__ __align__(16) float sm[];
    float* ws   = sm;
    float* hsh  = ws + RPC * WS;
    float* ghx  = hsh + 4 * HID;
    float* rbuf = ghx + 3 * 4 * 64;

    const int tid = threadIdx.x;
    const uint32_t rank = ctarank();

    for (int i = tid; i < RPC * 64; i += 256) {
        int r = i >> 6;
        int k4 = (i & 63) << 2;
        *(float4*)&ws[r * WS + k4] =
            *(const float4*)&whh[((size_t)(rank * RPC + r)) * 256 + k4];
    }
    for (int i = tid; i < 4 * HID; i += 256) hsh[i] = 0.0f;

    const uint32_t hsh_a = smem_u32(hsh);
    const uint32_t ghx_a = smem_u32(ghx);
    cluster_sync_();

    const int hl = tid & 63;
    const int bb = tid >> 6;
    const int hg = (int)rank * 64 + hl;

    for (int t = 0; t < 16; ++t) {
        float ir, ii, inn;
        {
            size_t row = (size_t)(ROWS_MAIN + t * 4 + bb);
            const float* gp = &g_gi[row * 768];
            ir = gp[hg]; ii = gp[256 + hg]; inn = gp[512 + hg];
        }
        if (tid < RPC) {
            const int rg = (int)rank * RPC + tid;
            float acc[4];
            const float bv = bhh[rg];
            #pragma unroll
            for (int b = 0; b < 4; ++b) acc[b] = bv;
            const float* wr = &ws[tid * WS];
            #pragma unroll 4
            for (int k = 0; k < 256; k += 4) {
                float4 w = *(const float4*)&wr[k];
                #pragma unroll
                for (int b = 0; b < 4; ++b) {
                    float4 h4 = *(const float4*)&hsh[b * HID + k];
                    acc[b] += w.x * h4.x + w.y * h4.y + w.z * h4.z + w.w * h4.w;
                }
            }
            const int chunk = rg >> 8;
            const int hv = rg & 255;
            const uint32_t owner = (uint32_t)(hv >> 6);
            const int hvl = hv & 63;
            #pragma unroll
            for (int b = 0; b < 4; ++b) {
                uint32_t addr = ghx_a + (uint32_t)(((chunk * 4 + b) * 64 + hvl) * 4);
                st_cluster_f32(addr, owner, acc[b]);
            }
        }
        cluster_sync_();
        {
            float hr = ghx[(0 * 4 + bb) * 64 + hl];
            float hi = ghx[(1 * 4 + bb) * 64 + hl];
            float hn = ghx[(2 * 4 + bb) * 64 + hl];
            float r = sigmoidf_(ir + hr);
            float z = sigmoidf_(ii + hi);
            float n = tanhf(inn + r * hn);
            float hold = hsh[bb * HID + hg];
            float hy = n + z * (hold - n);
            rbuf[bb * 64 + hl] = r;
            uint32_t addr = hsh_a + (uint32_t)((bb * HID + hg) * 4);
            #pragma unroll
            for (uint32_t rk = 0; rk < CSIZE; ++rk)
                st_cluster_f32(addr, rk, hy);
        }
        __syncthreads();
        if (tid < 64) {
            float s = 0.f;
            #pragma unroll
            for (int b = 0; b < 4; ++b) s += rbuf[b * 64 + tid];
            g_gates[t * 256 + (int)rank * 64 + tid] = s * 0.25f;
        }
        cluster_sync_();
    }
}

// ---------------------------------------------------------------------------
// Kernel C v3 (fixed): row-partitioned. 512 threads = (vl 64) x (ks 8).
// Step: prefetch -> wait(bar[t&1]) (t>0) -> re-arm -> FFMA over hbuf[t&1]
// -> STS red -> sync -> tid<64: reduce, GRU, STG out, broadcast h' unless
// last step. Ships(t) are consumed by wait(t+1); last step ships skipped and
// a trailing cluster sync drains everything before any CTA exits.
// ---------------------------------------------------------------------------
#define TXB2 2048u

__global__ void __launch_bounds__(512, 1) __cluster_dims__(CSIZE, 1, 1)
kC(const float* __restrict__ whh, const float* __restrict__ bhh,
   float* __restrict__ out)
{
    __shared__ __align__(16) float hbuf[2][2][256];   // [parity][batch][h]
    __shared__ __align__(16) float red[6][8][64];     // [g*2+b][ks][vl]
    __shared__ __align__(8) unsigned long long mbar[2];

    const int tid = threadIdx.x;
    const uint32_t rank = ctarank();
    const int cl = blockIdx.x >> 2;
    const int vl = tid & 63;
    const int ks = tid >> 6;

    // weights: rows g*256 + 64*rank + vl, k = ks*32 + [0,32)
    ull wreg[3][16];
    {
        #pragma unroll
        for (int g = 0; g < 3; ++g) {
            const float* wr = whh + ((size_t)(g * 256 + 64 * (int)rank + vl)) * 256 + ks * 32;
            #pragma unroll
            for (int i = 0; i < 32; i += 4) {
                ulonglong2 v = *(const ulonglong2*)&wr[i];
                wreg[g][i / 2]     = v.x;
                wreg[g][i / 2 + 1] = v.y;
            }
        }
    }

    // init hbuf[0] (t=0 reads zeros)
    hbuf[0][tid >> 8][tid & 255] = 0.0f;

    const uint32_t mb_a = smem_u32(&mbar[0]);
    if (tid == 0) {
        mbar_init(mb_a, 1);
        mbar_init(mb_a + 8, 1);
        mbar_arrive_expect(mb_a, TXB2);       // first use: wait at t=2 (ships of t=1)
        mbar_arrive_expect(mb_a + 8, TXB2);   // first use: wait at t=1 (ships of t=0)
    }

    // epilogue constants (tid < 64): eb = batch, eu = h-pair index
    const int eb = tid >> 5;
    const int eu = tid & 31;
    const int hg0 = 64 * (int)rank + 2 * eu;
    const int b_glob = cl * 2 + eb;
    const uint32_t hbuf_a = smem_u32(&hbuf[0][0][0]);

    cluster_sync_();   // barriers armed + hbuf[0] zeroed everywhere

    for (int t = 0; t < T_STEPS; ++t) {
        const int p = t & 1;

        // ---- prefetch gi, biases, gate (tid<64) -- overlaps wait latency ----
        float2 gir, gii, gin, ggp, bhr, bhi, bhn;
        if (tid < 64) {
            const float* gp = &g_gi[((size_t)t * BATCH + b_glob) * 768 + hg0];
            gir = *(const float2*)&gp[0];
            gii = *(const float2*)&gp[256];
            gin = *(const float2*)&gp[512];
            bhr = *(const float2*)&bhh[hg0];
            bhi = *(const float2*)&bhh[256 + hg0];
            bhn = *(const float2*)&bhh[512 + hg0];
            ggp = make_float2(1.0f, 1.0f);
            if (t < 16) ggp = *(const float2*)&g_gates[t * 256 + hg0];
        }

        // ---- wait for hbuf[p] completeness (ships of step t-1) ----
        if (t > 0) {
            uint32_t parity = ((((uint32_t)t + 1) >> 1) & 1u) ^ 1u;
            mbar_wait_parity(mb_a + 8u * (uint32_t)p, parity);
            if (tid == 0)
                mbar_arrive_expect(mb_a + 8u * (uint32_t)p, TXB2);  // for step t+2
        }

        // ---- full-k partial for this thread's 3 rows x 2 batches ----
        ull acc[3][2];
        #pragma unroll
        for (int g = 0; g < 3; ++g) { acc[g][0] = 0ull; acc[g][1] = 0ull; }
        {
            const float* h0p = &hbuf[p][0][ks * 32];
            const float* h1p = &hbuf[p][1][ks * 32];
            #pragma unroll
            for (int i = 0; i < 32; i += 4) {
                ulonglong2 h0 = *(const ulonglong2*)&h0p[i];
                ulonglong2 h1 = *(const ulonglong2*)&h1p[i];
                #pragma unroll
                for (int g = 0; g < 3; ++g) {
                    ull wa = wreg[g][i / 2], wb2 = wreg[g][i / 2 + 1];
                    fma2(acc[g][0], wa, h0.x); fma2(acc[g][0], wb2, h0.y);
                    fma2(acc[g][1], wa, h1.x); fma2(acc[g][1], wb2, h1.y);
                }
            }
        }
        #pragma unroll
        for (int g = 0; g < 3; ++g) {
            float x0, y0, x1, y1;
            unpk(acc[g][0], x0, y0);
            unpk(acc[g][1], x1, y1);
            red[g * 2 + 0][ks][vl] = x0 + y0;
            red[g * 2 + 1][ks][vl] = x1 + y1;
        }
        __syncthreads();

        // ---- epilogue (tid<64): reduce 8 slices, 2 GRU cells, broadcast ----
        if (tid < 64) {
            float2 sr = make_float2(0.f, 0.f), si = sr, sn = sr;
            #pragma unroll
            for (int k = 0; k < 8; ++k) {
                float2 a = *(const float2*)&red[0 * 2 + eb][k][2 * eu];
                float2 b = *(const float2*)&red[1 * 2 + eb][k][2 * eu];
                float2 c = *(const float2*)&red[2 * 2 + eb][k][2 * eu];
                sr.x += a.x; sr.y += a.y;
                si.x += b.x; si.y += b.y;
                sn.x += c.x; sn.y += c.y;
            }
            float2 hold = *(const float2*)&hbuf[p][eb][hg0];
            float r0 = sigm_(gir.x + bhr.x + sr.x);
            float r1 = sigm_(gir.y + bhr.y + sr.y);
            float z0 = sigm_(gii.x + bhi.x + si.x);
            float z1 = sigm_(gii.y + bhi.y + si.y);
            float n0 = tanh_(gin.x + r0 * (bhn.x + sn.x));
            float n1 = tanh_(gin.y + r1 * (bhn.y + sn.y));
            float hy0 = n0 + z0 * (hold.x - n0);
            float hy1 = n1 + z1 * (hold.y - n1);
            *(float2*)&out[((size_t)t * BATCH + b_glob) * HID + hg0] =
                make_float2(hy0, hy1);
            if (t != T_STEPS - 1) {   // last step's h' is dead: skipping keeps
                hy0 *= ggp.x;         // no st.async in flight at kernel exit
                hy1 *= ggp.y;
                const uint32_t lofs = hbuf_a + (uint32_t)((((p ^ 1) * 2 + eb) * 256 + hg0) * 4);
                const uint32_t lbar = mb_a + 8u * (uint32_t)(p ^ 1);
                #pragma unroll
                for (uint32_t rk = 0; rk < CSIZE; ++rk) {
                    uint32_t ra = mapa_addr(lofs, rk);
                    uint32_t rb = mapa_addr(lbar, rk);
                    st_async_2f(ra, hy0, hy1, rb);
                }
            }
        }
        // no tail sync: next step's wait is gated by our ships, which follow
        // all red/hold reads in per-thread program order.
    }

    // drain: keep every CTA resident until all cluster traffic has settled
    cluster_sync_();
}

// ---------------------------------------------------------------------------
extern "C" void kernel_launch(void* const* d_in, const int* in_sizes, int n_in,
                              void* d_out, int out_size)
{
    const float* x   = (const float*)d_in[0];
    const float* wmk = (const float*)d_in[1];
    const float* wih = (const float*)d_in[2];
    const float* whh = (const float*)d_in[3];
    const float* bih = (const float*)d_in[4];
    const float* bhh = (const float*)d_in[5];
    float* out = (float*)d_out;

    constexpr int SMEM_A   = 2 * 2 * 32 * BR2 * 4;
    constexpr int SMEM_KEY = (RPC * WS + 4 * HID + 3 * 4 * 64 + 4 * 64) * 4;

    cudaFuncSetAttribute((const void*)kA,
                         cudaFuncAttributeMaxDynamicSharedMemorySize, SMEM_A);
    cudaFuncSetAttribute((const void*)kB,
                         cudaFuncAttributeMaxDynamicSharedMemorySize, SMEM_KEY);

    dim3 gA(6, 1025);
    kA<<<gA, 256, SMEM_A>>>(x, wmk, wih, bih);
    kB<<<CSIZE, 256, SMEM_KEY>>>(whh, bhh);
    kC<<<32 * CSIZE, 512>>>(whh, bhh, out);
}